// round 3
// baseline (speedup 1.0000x reference)
#include <cuda_runtime.h>
#include <cuda_bf16.h>
#include <mma.h>
#include <cstdint>
#include <cstddef>

using namespace nvcuda;

// ---------------- problem constants ----------------
#define DD     1024      // K
#define PCOLS  405       // 1 + 80 + 324
#define BN     96        // CTA N tile
#define NT     5         // N tiles
#define PPAD   (BN * NT) // 480 padded cols
#define NF     300
#define BM     128       // CTA M tile
#define BK     32        // K per stage
#define NCHUNK (DD / BK)
#define NSTAGE 3

// smem: [0,2048) bias; stages at 2048, each: A 128x36 floats, B 96x36 floats
#define LDA      36
#define A_BYTES  (BM * LDA * 4)          // 18432
#define B_BYTES  (BN * LDA * 4)          // 13824
#define STAGE_SZ (A_BYTES + B_BYTES)     // 32256
#define SMEM_DYN (2048 + NSTAGE * STAGE_SZ)   // 98816 < 228KB
#define LDC      100                     // epilogue C buffer stride (128x100 = 51200B, reuses stages)

// ---------------- device scratch ----------------
__device__ float g_sm[80 * NF];
__device__ float g_Wt[(size_t)PPAD * DD];
__device__ float g_bias[PPAD];

__device__ __forceinline__ float to_tf32(float f) {
    float r; asm("cvt.rna.tf32.f32 %0, %1;" : "=f"(r) : "f"(f)); return r;
}

// ---------------- kernel A: normalize sem_matrix rows, scale by 8 ----------------
__global__ void k_norm(const float* __restrict__ semm) {
    int c = blockIdx.x, t = threadIdx.x;
    float ss = 0.f;
    for (int f = t; f < NF; f += 128) { float v = semm[c * NF + f]; ss += v * v; }
    for (int o = 16; o; o >>= 1) ss += __shfl_xor_sync(0xffffffffu, ss, o);
    __shared__ float ws[4];
    if ((t & 31) == 0) ws[t >> 5] = ss;
    __syncthreads();
    float scale = 8.0f * rsqrtf(ws[0] + ws[1] + ws[2] + ws[3]);
    for (int f = t; f < NF; f += 128) g_sm[c * NF + f] = semm[c * NF + f] * scale;
}

// ---------------- kernel B: build fused W (tf32-pre-rounded) + bias ----------------
__global__ void k_build(const float* __restrict__ Wcls, const float* __restrict__ bcls,
                        const float* __restrict__ Wsem, const float* __restrict__ bsem,
                        const float* __restrict__ Wbb,  const float* __restrict__ bbb) {
    __shared__ float srow[NF];
    int r = blockIdx.x, t = threadIdx.x;
    if (r == 0) {
        for (int d = t; d < DD; d += 256) g_Wt[d] = to_tf32(Wcls[d]);
        if (t == 0) g_bias[0] = bcls[0];
    } else if (r <= 80) {
        int c = r - 1;
        for (int f = t; f < NF; f += 256) srow[f] = g_sm[c * NF + f];
        __syncthreads();
        float a0 = 0.f, a1 = 0.f, a2 = 0.f, a3 = 0.f;
        for (int f = 0; f < NF; f++) {
            float s = srow[f];
            const float* wp = Wsem + (size_t)f * DD + t;
            a0 += s * wp[0]; a1 += s * wp[256]; a2 += s * wp[512]; a3 += s * wp[768];
        }
        float* wo = g_Wt + (size_t)r * DD + t;
        wo[0] = to_tf32(a0); wo[256] = to_tf32(a1); wo[512] = to_tf32(a2); wo[768] = to_tf32(a3);
        if (t == 0) {
            float b = 0.f;
            for (int f = 0; f < NF; f++) b += srow[f] * bsem[f];
            g_bias[r] = b;
        }
    } else if (r < PCOLS) {
        int i = r - 81;
        for (int d = t; d < DD; d += 256) g_Wt[(size_t)r * DD + d] = to_tf32(Wbb[(size_t)i * DD + d]);
        if (t == 0) g_bias[r] = bbb[i];
    } else {
        for (int d = t; d < DD; d += 256) g_Wt[(size_t)r * DD + d] = 0.f;
        if (t == 0) g_bias[r] = 0.f;
    }
}

// ---------------- main GEMM: wmma tf32, 3-stage cp.async pipeline ----------------
__device__ __forceinline__ void cpa16(uint32_t dst, const void* src) {
    asm volatile("cp.async.cg.shared.global [%0], [%1], 16;" :: "r"(dst), "l"(src));
}
__device__ __forceinline__ uint32_t smem_u32(const void* p) {
    uint32_t a;
    asm("{ .reg .u64 t; cvta.to.shared.u64 t, %1; cvt.u32.u64 %0, t; }" : "=r"(a) : "l"(p));
    return a;
}

__device__ __forceinline__ void issue_stage(uint32_t sbase, const float* __restrict__ xrow0,
                                            const float* __restrict__ wrow0, int c, int tid) {
    const float* xs = xrow0 + c * BK;
    const float* ws = wrow0 + c * BK;
    // A: 128 rows x 8 float4 = 1024 chunks; 256 thr x 4
#pragma unroll
    for (int i = 0; i < 4; i++) {
        int seg = tid + i * 256;
        int row = seg >> 3, q = seg & 7;
        cpa16(sbase + (uint32_t)(row * LDA + q * 4) * 4, xs + (size_t)row * DD + q * 4);
    }
    // B: 96 rows x 8 float4 = 768 chunks; 256 thr x 3
#pragma unroll
    for (int i = 0; i < 3; i++) {
        int seg = tid + i * 256;
        int row = seg >> 3, q = seg & 7;
        cpa16(sbase + (uint32_t)A_BYTES + (uint32_t)(row * LDA + q * 4) * 4,
              ws + (size_t)row * DD + q * 4);
    }
    asm volatile("cp.async.commit_group;" ::: "memory");
}

__global__ __launch_bounds__(256, 1) void k_main(const float* __restrict__ x,
                                                 float* __restrict__ out, int N) {
    extern __shared__ char sm[];
    const int tid = threadIdx.x, wid = tid >> 5;
    const int warp_m = wid & 3;         // 4 in M: 32 rows each
    const int warp_n = wid >> 2;        // 2 in N: 48 cols each
    const int nt = blockIdx.x;          // N tile 0..4
    const size_t row0 = (size_t)blockIdx.y * BM;
    const size_t NS = (size_t)N * 81;

    float* sBias = (float*)sm;
    for (int i = tid; i < PPAD; i += 256) sBias[i] = g_bias[i];

    uint32_t st_u32[NSTAGE];
    float*   st_f32[NSTAGE];
#pragma unroll
    for (int s = 0; s < NSTAGE; s++) {
        st_f32[s] = (float*)(sm + 2048 + s * STAGE_SZ);
        st_u32[s] = smem_u32(st_f32[s]);
    }

    const float* xrow0 = x + row0 * DD;
    const float* wrow0 = g_Wt + (size_t)nt * BN * DD;

    wmma::fragment<wmma::accumulator, 16, 16, 8, float> acc[2][3];
#pragma unroll
    for (int i = 0; i < 2; i++)
#pragma unroll
        for (int j = 0; j < 3; j++) wmma::fill_fragment(acc[i][j], 0.f);

    issue_stage(st_u32[0], xrow0, wrow0, 0, tid);
    issue_stage(st_u32[1], xrow0, wrow0, 1, tid);

    for (int c = 0; c < NCHUNK; c++) {
        int s = c % NSTAGE;
        if (c == NCHUNK - 1) asm volatile("cp.async.wait_group 0;" ::: "memory");
        else                 asm volatile("cp.async.wait_group 1;" ::: "memory");
        __syncthreads();
        if (c + 2 < NCHUNK)
            issue_stage(st_u32[(c + 2) % NSTAGE], xrow0, wrow0, c + 2, tid);

        const float* sA = st_f32[s];
        const float* sB = st_f32[s] + BM * LDA;
#pragma unroll
        for (int kk = 0; kk < BK; kk += 8) {
            wmma::fragment<wmma::matrix_a, 16, 16, 8, wmma::precision::tf32, wmma::row_major> af[2];
            wmma::fragment<wmma::matrix_b, 16, 16, 8, wmma::precision::tf32, wmma::col_major> bf[3];
#pragma unroll
            for (int i = 0; i < 2; i++) {
                wmma::load_matrix_sync(af[i], sA + (warp_m * 32 + i * 16) * LDA + kk, LDA);
#pragma unroll
                for (int e = 0; e < af[i].num_elements; e++)
                    af[i].x[e] = wmma::__float_to_tf32(af[i].x[e]);
            }
#pragma unroll
            for (int j = 0; j < 3; j++)
                wmma::load_matrix_sync(bf[j], sB + (warp_n * 48 + j * 16) * LDA + kk, LDA);
#pragma unroll
            for (int i = 0; i < 2; i++)
#pragma unroll
                for (int j = 0; j < 3; j++)
                    wmma::mma_sync(acc[i][j], af[i], bf[j], acc[i][j]);
        }
        __syncthreads();
    }

    // ---- epilogue: frags -> smem -> biased scatter ----
    float* sC = (float*)(sm + 2048);   // 128 x LDC floats, reuses stage memory
#pragma unroll
    for (int i = 0; i < 2; i++)
#pragma unroll
        for (int j = 0; j < 3; j++)
            wmma::store_matrix_sync(sC + (warp_m * 32 + i * 16) * LDC + warp_n * 48 + j * 16,
                                    acc[i][j], LDC, wmma::mem_row_major);
    __syncthreads();

    float* outb = out + NS;
    const int jbase = nt * BN;
    for (int e = tid; e < BM * BN; e += 256) {
        int row = e / BN, n = e % BN;
        int j = jbase + n;
        if (j < PCOLS) {
            float v = sC[row * LDC + n] + sBias[j];
            size_t gr = row0 + row;
            if (j < 81) out[gr * 81 + j] = v;
            else        outb[gr * 324 + (j - 81)] = v;
        }
    }
}

// ---------------- launch ----------------
extern "C" void kernel_launch(void* const* d_in, const int* in_sizes, int n_in,
                              void* d_out, int out_size) {
    const float* x    = (const float*)d_in[0];
    const float* Wcls = (const float*)d_in[1];
    const float* bcls = (const float*)d_in[2];
    const float* Wsem = (const float*)d_in[3];
    const float* bsem = (const float*)d_in[4];
    const float* Wbb  = (const float*)d_in[5];
    const float* bbb  = (const float*)d_in[6];
    const float* semm = (const float*)d_in[7];
    float* out = (float*)d_out;
    int N = in_sizes[0] / DD;

    cudaFuncSetAttribute(k_main, cudaFuncAttributeMaxDynamicSharedMemorySize, SMEM_DYN);

    k_norm<<<80, 128>>>(semm);
    k_build<<<PPAD, 256>>>(Wcls, bcls, Wsem, bsem, Wbb, bbb);
    dim3 grid(NT, N / BM);
    k_main<<<grid, 256, SMEM_DYN>>>(x, out, N);
}

// round 4
// speedup vs baseline: 1.1385x; 1.1385x over previous
#include <cuda_runtime.h>
#include <cuda_bf16.h>
#include <mma.h>
#include <cstdint>
#include <cstddef>

using namespace nvcuda;

// ---------------- problem constants ----------------
#define DD     1024      // K
#define PCOLS  405       // 1 + 80 + 324
#define BN     96        // CTA N tile
#define NT     5         // N tiles (last is mostly dead, predicated off)
#define PPAD   (BN * NT) // 480 padded cols
#define NF     300
#define BM     128       // CTA M tile
#define BK     32        // K per stage
#define NCHUNK (DD / BK)
#define NSTAGE 3

#define LDA      36
#define A_BYTES  (BM * LDA * 4)          // 18432
#define B_BYTES  (BN * LDA * 4)          // 13824
#define STAGE_SZ (A_BYTES + B_BYTES)     // 32256
#define SMEM_DYN (2048 + NSTAGE * STAGE_SZ)   // 98816 -> 2 CTAs/SM
#define LDC      100

// ---------------- device scratch ----------------
__device__ float g_sm[80 * NF];
__device__ float g_Wt[(size_t)PPAD * DD];
__device__ float g_bias[PPAD];

__device__ __forceinline__ float to_tf32(float f) {
    float r; asm("cvt.rna.tf32.f32 %0, %1;" : "=f"(r) : "f"(f)); return r;
}

// ---------------- kernel A: normalize sem_matrix rows, scale by 8 ----------------
__global__ void k_norm(const float* __restrict__ semm) {
    int c = blockIdx.x, t = threadIdx.x;
    float ss = 0.f;
    for (int f = t; f < NF; f += 128) { float v = semm[c * NF + f]; ss += v * v; }
    for (int o = 16; o; o >>= 1) ss += __shfl_xor_sync(0xffffffffu, ss, o);
    __shared__ float ws[4];
    if ((t & 31) == 0) ws[t >> 5] = ss;
    __syncthreads();
    float scale = 8.0f * rsqrtf(ws[0] + ws[1] + ws[2] + ws[3]);
    for (int f = t; f < NF; f += 128) g_sm[c * NF + f] = semm[c * NF + f] * scale;
}

// ---------------- kernel B: build fused W (tf32-pre-rounded) + bias ----------------
__global__ void k_build(const float* __restrict__ Wcls, const float* __restrict__ bcls,
                        const float* __restrict__ Wsem, const float* __restrict__ bsem,
                        const float* __restrict__ Wbb,  const float* __restrict__ bbb) {
    __shared__ float srow[NF];
    int r = blockIdx.x, t = threadIdx.x;
    if (r == 0) {
        for (int d = t; d < DD; d += 256) g_Wt[d] = to_tf32(Wcls[d]);
        if (t == 0) g_bias[0] = bcls[0];
    } else if (r <= 80) {
        int c = r - 1;
        for (int f = t; f < NF; f += 256) srow[f] = g_sm[c * NF + f];
        __syncthreads();
        float a0 = 0.f, a1 = 0.f, a2 = 0.f, a3 = 0.f;
        for (int f = 0; f < NF; f++) {
            float s = srow[f];
            const float* wp = Wsem + (size_t)f * DD + t;
            a0 += s * wp[0]; a1 += s * wp[256]; a2 += s * wp[512]; a3 += s * wp[768];
        }
        float* wo = g_Wt + (size_t)r * DD + t;
        wo[0] = to_tf32(a0); wo[256] = to_tf32(a1); wo[512] = to_tf32(a2); wo[768] = to_tf32(a3);
        if (t == 0) {
            float b = 0.f;
            for (int f = 0; f < NF; f++) b += srow[f] * bsem[f];
            g_bias[r] = b;
        }
    } else if (r < PCOLS) {
        int i = r - 81;
        for (int d = t; d < DD; d += 256) g_Wt[(size_t)r * DD + d] = to_tf32(Wbb[(size_t)i * DD + d]);
        if (t == 0) g_bias[r] = bbb[i];
    } else {
        for (int d = t; d < DD; d += 256) g_Wt[(size_t)r * DD + d] = 0.f;
        if (t == 0) g_bias[r] = 0.f;
    }
}

// ---------------- main GEMM: wmma tf32, 3-stage cp.async pipeline, occ=2 ----------------
__device__ __forceinline__ void cpa16(uint32_t dst, const void* src) {
    asm volatile("cp.async.cg.shared.global [%0], [%1], 16;" :: "r"(dst), "l"(src));
}
__device__ __forceinline__ uint32_t smem_u32(const void* p) {
    uint32_t a;
    asm("{ .reg .u64 t; cvta.to.shared.u64 t, %1; cvt.u32.u64 %0, t; }" : "=r"(a) : "l"(p));
    return a;
}

__device__ __forceinline__ void issue_stage(uint32_t sbase, const float* __restrict__ xrow0,
                                            const float* __restrict__ wrow0, int c, int tid) {
    const float* xs = xrow0 + c * BK;
    const float* ws = wrow0 + c * BK;
#pragma unroll
    for (int i = 0; i < 4; i++) {
        int seg = tid + i * 256;
        int row = seg >> 3, q = seg & 7;
        cpa16(sbase + (uint32_t)(row * LDA + q * 4) * 4, xs + (size_t)row * DD + q * 4);
    }
#pragma unroll
    for (int i = 0; i < 3; i++) {
        int seg = tid + i * 256;
        int row = seg >> 3, q = seg & 7;
        cpa16(sbase + (uint32_t)A_BYTES + (uint32_t)(row * LDA + q * 4) * 4,
              ws + (size_t)row * DD + q * 4);
    }
    asm volatile("cp.async.commit_group;" ::: "memory");
}

__global__ __launch_bounds__(256, 2) void k_main(const float* __restrict__ x,
                                                 float* __restrict__ out, int N) {
    extern __shared__ char sm[];
    const int tid = threadIdx.x, wid = tid >> 5;
    const int warp_m = wid & 3;         // 4 in M: 32 rows each
    const int warp_n = wid >> 2;        // 2 in N: 48 cols each
    const int nt = blockIdx.x;
    const size_t row0 = (size_t)blockIdx.y * BM;
    const size_t NS = (size_t)N * 81;

    // how many 16-col fragments of this warp's 48-col slice hold live columns
    const int col0 = nt * BN + warp_n * 48;
    int jcount = 0;
    if (col0 < PCOLS) jcount = min(3, (PCOLS - col0 + 15) >> 4);

    float* sBias = (float*)sm;
    for (int i = tid; i < PPAD; i += 256) sBias[i] = g_bias[i];

    uint32_t st_u32[NSTAGE];
    float*   st_f32[NSTAGE];
#pragma unroll
    for (int s = 0; s < NSTAGE; s++) {
        st_f32[s] = (float*)(sm + 2048 + s * STAGE_SZ);
        st_u32[s] = smem_u32(st_f32[s]);
    }

    const float* xrow0 = x + row0 * DD;
    const float* wrow0 = g_Wt + (size_t)nt * BN * DD;

    wmma::fragment<wmma::accumulator, 16, 16, 8, float> acc[2][3];
#pragma unroll
    for (int i = 0; i < 2; i++)
#pragma unroll
        for (int j = 0; j < 3; j++) wmma::fill_fragment(acc[i][j], 0.f);

    issue_stage(st_u32[0], xrow0, wrow0, 0, tid);
    issue_stage(st_u32[1], xrow0, wrow0, 1, tid);

    for (int c = 0; c < NCHUNK; c++) {
        int s = c % NSTAGE;
        if (c == NCHUNK - 1) asm volatile("cp.async.wait_group 0;" ::: "memory");
        else                 asm volatile("cp.async.wait_group 1;" ::: "memory");
        __syncthreads();
        if (c + 2 < NCHUNK)
            issue_stage(st_u32[(c + 2) % NSTAGE], xrow0, wrow0, c + 2, tid);

        if (jcount > 0) {
            const float* sA = st_f32[s];
            const float* sB = st_f32[s] + BM * LDA;
#pragma unroll
            for (int kk = 0; kk < BK; kk += 8) {
                wmma::fragment<wmma::matrix_a, 16, 16, 8, wmma::precision::tf32, wmma::row_major> af[2];
                wmma::fragment<wmma::matrix_b, 16, 16, 8, wmma::precision::tf32, wmma::col_major> bf[3];
#pragma unroll
                for (int i = 0; i < 2; i++) {
                    wmma::load_matrix_sync(af[i], sA + (warp_m * 32 + i * 16) * LDA + kk, LDA);
#pragma unroll
                    for (int e = 0; e < af[i].num_elements; e++)
                        af[i].x[e] = wmma::__float_to_tf32(af[i].x[e]);
                }
#pragma unroll
                for (int j = 0; j < 3; j++)
                    if (j < jcount)
                        wmma::load_matrix_sync(bf[j], sB + (warp_n * 48 + j * 16) * LDA + kk, LDA);
#pragma unroll
                for (int i = 0; i < 2; i++)
#pragma unroll
                    for (int j = 0; j < 3; j++)
                        if (j < jcount)
                            wmma::mma_sync(acc[i][j], af[i], bf[j], acc[i][j]);
            }
        }
        __syncthreads();
    }

    // ---- epilogue: frags -> smem -> biased scatter ----
    float* sC = (float*)(sm + 2048);
#pragma unroll
    for (int i = 0; i < 2; i++)
#pragma unroll
        for (int j = 0; j < 3; j++)
            if (j < jcount)
                wmma::store_matrix_sync(sC + (warp_m * 32 + i * 16) * LDC + warp_n * 48 + j * 16,
                                        acc[i][j], LDC, wmma::mem_row_major);
    __syncthreads();

    float* outb = out + NS;
    const int jbase = nt * BN;
    const int ncols = min(BN, PCOLS - jbase);   // live cols in this tile
    for (int e = tid; e < BM * ncols; e += 256) {
        int row = e / ncols, n = e % ncols;
        int j = jbase + n;
        float v = sC[row * LDC + n] + sBias[j];
        size_t gr = row0 + row;
        if (j < 81) out[gr * 81 + j] = v;
        else        outb[gr * 324 + (j - 81)] = v;
    }
}

// ---------------- launch ----------------
extern "C" void kernel_launch(void* const* d_in, const int* in_sizes, int n_in,
                              void* d_out, int out_size) {
    const float* x    = (const float*)d_in[0];
    const float* Wcls = (const float*)d_in[1];
    const float* bcls = (const float*)d_in[2];
    const float* Wsem = (const float*)d_in[3];
    const float* bsem = (const float*)d_in[4];
    const float* Wbb  = (const float*)d_in[5];
    const float* bbb  = (const float*)d_in[6];
    const float* semm = (const float*)d_in[7];
    float* out = (float*)d_out;
    int N = in_sizes[0] / DD;

    cudaFuncSetAttribute(k_main, cudaFuncAttributeMaxDynamicSharedMemorySize, SMEM_DYN);

    k_norm<<<80, 128>>>(semm);
    k_build<<<PPAD, 256>>>(Wcls, bcls, Wsem, bsem, Wbb, bbb);
    dim3 grid(NT, N / BM);
    k_main<<<grid, 256, SMEM_DYN>>>(x, out, N);
}

// round 5
// speedup vs baseline: 1.8951x; 1.6646x over previous
#include <cuda_runtime.h>
#include <cstdint>
#include <cstddef>

// ---------------- problem constants ----------------
#define DD     1024
#define PCOLS  405       // 1 + 80 + 324
#define BN     96
#define NT     5
#define PPAD   (BN * NT) // 480
#define NF     300
#define BM     128
#define BK     32
#define NCHUNK (DD / BK)
#define NSTAGE 3

#define A_BYTES  (BM * 128)              // 16384 (128 rows x 32 tf32 = 128B)
#define B_BYTES  (BN * 128)              // 12288
#define STAGE_SZ (A_BYTES + B_BYTES)     // 28672
#define SMEM_DYN (2048 + NSTAGE * STAGE_SZ)  // 88064 -> 2 CTAs/SM
#define LDC      104

// ---------------- device scratch ----------------
__device__ float g_sm[80 * NF];
__device__ float g_Wt[(size_t)PPAD * DD];
__device__ float g_bias[PPAD];

__device__ __forceinline__ float to_tf32(float f) {
    float r; asm("cvt.rna.tf32.f32 %0, %1;" : "=f"(r) : "f"(f)); return r;
}
__device__ __forceinline__ uint32_t cvt_tf32_u(uint32_t v) {
    uint32_t r; asm("cvt.rna.tf32.f32 %0, %1;" : "=r"(r) : "r"(v)); return r;
}
__device__ __forceinline__ uint32_t smem_u32(const void* p) {
    uint32_t a;
    asm("{ .reg .u64 t; cvta.to.shared.u64 t, %1; cvt.u32.u64 %0, t; }" : "=r"(a) : "l"(p));
    return a;
}
__device__ __forceinline__ void cpa16(uint32_t dst, const void* src) {
    asm volatile("cp.async.cg.shared.global [%0], [%1], 16;" :: "r"(dst), "l"(src));
}
__device__ __forceinline__ void ldsm4(uint32_t r[4], uint32_t addr) {
    asm volatile("ldmatrix.sync.aligned.m8n8.x4.shared.b16 {%0,%1,%2,%3}, [%4];"
        : "=r"(r[0]), "=r"(r[1]), "=r"(r[2]), "=r"(r[3]) : "r"(addr));
}
__device__ __forceinline__ void mma8(float d[4], const uint32_t a[4], uint32_t b0, uint32_t b1) {
    asm volatile(
        "mma.sync.aligned.m16n8k8.row.col.f32.tf32.tf32.f32 "
        "{%0,%1,%2,%3}, {%4,%5,%6,%7}, {%8,%9}, {%0,%1,%2,%3};"
        : "+f"(d[0]), "+f"(d[1]), "+f"(d[2]), "+f"(d[3])
        : "r"(a[0]), "r"(a[1]), "r"(a[2]), "r"(a[3]), "r"(b0), "r"(b1));
}

// ---------------- kernel A: normalize sem_matrix rows, scale by 8 ----------------
__global__ void k_norm(const float* __restrict__ semm) {
    int c = blockIdx.x, t = threadIdx.x;
    float ss = 0.f;
    for (int f = t; f < NF; f += 128) { float v = semm[c * NF + f]; ss += v * v; }
    for (int o = 16; o; o >>= 1) ss += __shfl_xor_sync(0xffffffffu, ss, o);
    __shared__ float ws[4];
    if ((t & 31) == 0) ws[t >> 5] = ss;
    __syncthreads();
    float scale = 8.0f * rsqrtf(ws[0] + ws[1] + ws[2] + ws[3]);
    for (int f = t; f < NF; f += 128) g_sm[c * NF + f] = semm[c * NF + f] * scale;
}

// ---------------- kernel B: build fused W (tf32-pre-rounded) + bias ----------------
__global__ void k_build(const float* __restrict__ Wcls, const float* __restrict__ bcls,
                        const float* __restrict__ Wsem, const float* __restrict__ bsem,
                        const float* __restrict__ Wbb,  const float* __restrict__ bbb) {
    __shared__ float srow[NF];
    int r = blockIdx.x, t = threadIdx.x;
    if (r == 0) {
        for (int d = t; d < DD; d += 256) g_Wt[d] = to_tf32(Wcls[d]);
        if (t == 0) g_bias[0] = bcls[0];
    } else if (r <= 80) {
        int c = r - 1;
        for (int f = t; f < NF; f += 256) srow[f] = g_sm[c * NF + f];
        __syncthreads();
        float a0 = 0.f, a1 = 0.f, a2 = 0.f, a3 = 0.f;
        for (int f = 0; f < NF; f++) {
            float s = srow[f];
            const float* wp = Wsem + (size_t)f * DD + t;
            a0 += s * wp[0]; a1 += s * wp[256]; a2 += s * wp[512]; a3 += s * wp[768];
        }
        float* wo = g_Wt + (size_t)r * DD + t;
        wo[0] = to_tf32(a0); wo[256] = to_tf32(a1); wo[512] = to_tf32(a2); wo[768] = to_tf32(a3);
        if (t == 0) {
            float b = 0.f;
            for (int f = 0; f < NF; f++) b += srow[f] * bsem[f];
            g_bias[r] = b;
        }
    } else if (r < PCOLS) {
        int i = r - 81;
        for (int d = t; d < DD; d += 256) g_Wt[(size_t)r * DD + d] = to_tf32(Wbb[(size_t)i * DD + d]);
        if (t == 0) g_bias[r] = bbb[i];
    } else {
        for (int d = t; d < DD; d += 256) g_Wt[(size_t)r * DD + d] = 0.f;
        if (t == 0) g_bias[r] = 0.f;
    }
}

// ---------------- main GEMM: raw mma.tf32 + ldmatrix, 3-stage cp.async ----------------
__device__ __forceinline__ void issue_stage(uint32_t sbase, const float* __restrict__ xrow0,
                                            const float* __restrict__ wrow0, int c, int tid) {
    const float* xs = xrow0 + c * BK;
    const float* ws = wrow0 + c * BK;
#pragma unroll
    for (int i = 0; i < 8; i++) {               // A: 128 rows x 8 quads
        int seg = tid + i * 128;
        int row = seg >> 3, q = seg & 7;
        cpa16(sbase + (uint32_t)(row * 128 + ((q ^ (row & 7)) << 4)),
              xs + (size_t)row * DD + q * 4);
    }
#pragma unroll
    for (int i = 0; i < 6; i++) {               // B: 96 rows x 8 quads
        int seg = tid + i * 128;
        int row = seg >> 3, q = seg & 7;
        cpa16(sbase + (uint32_t)(A_BYTES + row * 128 + ((q ^ (row & 7)) << 4)),
              ws + (size_t)row * DD + q * 4);
    }
    asm volatile("cp.async.commit_group;" ::: "memory");
}

__global__ __launch_bounds__(128, 2) void k_main(const float* __restrict__ x,
                                                 float* __restrict__ out, int N) {
    extern __shared__ char sm[];
    const int tid = threadIdx.x, wid = tid >> 5, lane = tid & 31;
    const int warp_m = wid & 1;        // 2 in M: 64 rows each
    const int warp_n = wid >> 1;       // 2 in N: 48 cols each
    const int nt = blockIdx.x;
    const size_t row0 = (size_t)blockIdx.y * BM;
    const size_t NS = (size_t)N * 81;

    // live n8 blocks for this warp (6 max)
    const int col0w = nt * BN + warp_n * 48;
    const int njmax = max(0, min(6, (PCOLS - col0w + 7) >> 3));

    float* sBias = (float*)sm;                       // 96 floats for this tile
    for (int i = tid; i < BN; i += 128) sBias[i] = g_bias[nt * BN + i];

    uint32_t st_u32[NSTAGE];
#pragma unroll
    for (int s = 0; s < NSTAGE; s++) st_u32[s] = smem_u32(sm + 2048 + s * STAGE_SZ);

    const float* xrow0 = x + row0 * DD;
    const float* wrow0 = g_Wt + (size_t)nt * BN * DD;

    // per-thread ldmatrix rows (constant across k)
    int rA[4], rB[3];
    const int qbA = (lane >> 4) & 1;       // A quad bit from matrix group
    const int qbB = (lane >> 3) & 1;       // B quad bit
#pragma unroll
    for (int mi = 0; mi < 4; mi++)
        rA[mi] = warp_m * 64 + mi * 16 + ((lane >> 3) & 1) * 8 + (lane & 7);
#pragma unroll
    for (int gj = 0; gj < 3; gj++)
        rB[gj] = warp_n * 48 + gj * 16 + ((lane >> 4) & 1) * 8 + (lane & 7);

    float acc[4][6][4];
#pragma unroll
    for (int mi = 0; mi < 4; mi++)
#pragma unroll
        for (int nj = 0; nj < 6; nj++)
#pragma unroll
            for (int e = 0; e < 4; e++) acc[mi][nj][e] = 0.f;

    issue_stage(st_u32[0], xrow0, wrow0, 0, tid);
    issue_stage(st_u32[1], xrow0, wrow0, 1, tid);

    for (int c = 0; c < NCHUNK; c++) {
        int s = c % NSTAGE;
        if (c == NCHUNK - 1) asm volatile("cp.async.wait_group 0;" ::: "memory");
        else                 asm volatile("cp.async.wait_group 1;" ::: "memory");
        __syncthreads();   // stage c ready; stage (c+2)%3 fully consumed by all warps
        if (c + 2 < NCHUNK)
            issue_stage(st_u32[(c + 2) % NSTAGE], xrow0, wrow0, c + 2, tid);

        if (njmax > 0) {
            const uint32_t Ab = st_u32[s];
            const uint32_t Bb = st_u32[s] + A_BYTES;
#pragma unroll
            for (int kq2 = 0; kq2 < 4; kq2++) {   // k-step of 8 (two quads)
                uint32_t a[4][4];
#pragma unroll
                for (int mi = 0; mi < 4; mi++) {
                    int r = rA[mi];
                    ldsm4(a[mi], Ab + (uint32_t)(r * 128 + (((2 * kq2 + qbA) ^ (r & 7)) << 4)));
                }
#pragma unroll
                for (int mi = 0; mi < 4; mi++)
#pragma unroll
                    for (int e = 0; e < 4; e++) a[mi][e] = cvt_tf32_u(a[mi][e]);

                uint32_t b[3][4];
#pragma unroll
                for (int gj = 0; gj < 3; gj++) {
                    if (gj * 2 < njmax) {
                        int r = rB[gj];
                        ldsm4(b[gj], Bb + (uint32_t)(r * 128 + (((2 * kq2 + qbB) ^ (r & 7)) << 4)));
                    }
                }
#pragma unroll
                for (int mi = 0; mi < 4; mi++)
#pragma unroll
                    for (int nj = 0; nj < 6; nj++)
                        if (nj < njmax)
                            mma8(acc[mi][nj], a[mi], b[nj >> 1][(nj & 1) * 2], b[nj >> 1][(nj & 1) * 2 + 1]);
            }
        }
    }
    __syncthreads();

    // ---- epilogue: frags -> smem (transpose) -> biased scatter ----
    float* sC = (float*)(sm + 2048);
    const int tr = lane >> 2, tc2 = (lane & 3) * 2;
#pragma unroll
    for (int mi = 0; mi < 4; mi++)
#pragma unroll
        for (int nj = 0; nj < 6; nj++)
            if (nj < njmax) {
                int r = warp_m * 64 + mi * 16 + tr;
                int cc = warp_n * 48 + nj * 8 + tc2;
                *(float2*)&sC[r * LDC + cc]       = make_float2(acc[mi][nj][0], acc[mi][nj][1]);
                *(float2*)&sC[(r + 8) * LDC + cc] = make_float2(acc[mi][nj][2], acc[mi][nj][3]);
            }
    __syncthreads();

    float* outb = out + NS;
    const int jbase = nt * BN;
    const int ncols = min(BN, PCOLS - jbase);
    for (int e = tid; e < BM * ncols; e += 128) {
        int row = e / ncols, n = e % ncols;
        int j = jbase + n;
        float v = sC[row * LDC + n] + sBias[n];
        size_t gr = row0 + row;
        if (j < 81) out[gr * 81 + j] = v;
        else        outb[gr * 324 + (j - 81)] = v;
    }
}

// ---------------- launch ----------------
extern "C" void kernel_launch(void* const* d_in, const int* in_sizes, int n_in,
                              void* d_out, int out_size) {
    const float* x    = (const float*)d_in[0];
    const float* Wcls = (const float*)d_in[1];
    const float* bcls = (const float*)d_in[2];
    const float* Wsem = (const float*)d_in[3];
    const float* bsem = (const float*)d_in[4];
    const float* Wbb  = (const float*)d_in[5];
    const float* bbb  = (const float*)d_in[6];
    const float* semm = (const float*)d_in[7];
    float* out = (float*)d_out;
    int N = in_sizes[0] / DD;

    cudaFuncSetAttribute(k_main, cudaFuncAttributeMaxDynamicSharedMemorySize, SMEM_DYN);

    k_norm<<<80, 128>>>(semm);
    k_build<<<PPAD, 256>>>(Wcls, bcls, Wsem, bsem, Wbb, bbb);
    dim3 grid(NT, N / BM);
    k_main<<<grid, 128, SMEM_DYN>>>(x, out, N);
}

// round 6
// speedup vs baseline: 2.5627x; 1.3522x over previous
#include <cuda_runtime.h>
#include <cstdint>
#include <cstddef>

// ---------------- problem constants ----------------
#define DD     1024
#define PCOLS  405       // 1 + 80 + 324
#define BN     96
#define NT     5
#define PPAD   (BN * NT) // 480
#define NF     300
#define BM     128
#define BK     32
#define NCHUNK (DD / BK)
#define NSTAGE 3

#define A_BYTES  (BM * 128)              // 16384
#define B_BYTES  (BN * 128)              // 12288
#define STAGE_SZ (A_BYTES + B_BYTES)     // 28672
#define SMEM_DYN (2048 + NSTAGE * STAGE_SZ)  // 88064 -> 2 CTAs/SM
#define LDC      104

// ---------------- device scratch ----------------
__device__ float g_sm[80 * NF];
__device__ float g_Wt[(size_t)PPAD * DD];
__device__ float g_bias[PPAD];

__device__ __forceinline__ float to_tf32(float f) {
    float r; asm("cvt.rna.tf32.f32 %0, %1;" : "=f"(r) : "f"(f)); return r;
}
__device__ __forceinline__ uint32_t smem_u32(const void* p) {
    uint32_t a;
    asm("{ .reg .u64 t; cvta.to.shared.u64 t, %1; cvt.u32.u64 %0, t; }" : "=r"(a) : "l"(p));
    return a;
}
__device__ __forceinline__ void cpa16(uint32_t dst, const void* src) {
    asm volatile("cp.async.cg.shared.global [%0], [%1], 16;" :: "r"(dst), "l"(src));
}
__device__ __forceinline__ void ldsm4(uint32_t r[4], uint32_t addr) {
    asm volatile("ldmatrix.sync.aligned.m8n8.x4.shared.b16 {%0,%1,%2,%3}, [%4];"
        : "=r"(r[0]), "=r"(r[1]), "=r"(r[2]), "=r"(r[3]) : "r"(addr));
}
__device__ __forceinline__ void mma8(float d[4], const uint32_t a[4], uint32_t b0, uint32_t b1) {
    asm volatile(
        "mma.sync.aligned.m16n8k8.row.col.f32.tf32.tf32.f32 "
        "{%0,%1,%2,%3}, {%4,%5,%6,%7}, {%8,%9}, {%0,%1,%2,%3};"
        : "+f"(d[0]), "+f"(d[1]), "+f"(d[2]), "+f"(d[3])
        : "r"(a[0]), "r"(a[1]), "r"(a[2]), "r"(a[3]), "r"(b0), "r"(b1));
}

// ---------------- kernel A: normalize sem_matrix rows, scale by 8 ----------------
__global__ void k_norm(const float* __restrict__ semm) {
    int c = blockIdx.x, t = threadIdx.x;
    float ss = 0.f;
    for (int f = t; f < NF; f += 128) { float v = semm[c * NF + f]; ss += v * v; }
    for (int o = 16; o; o >>= 1) ss += __shfl_xor_sync(0xffffffffu, ss, o);
    __shared__ float ws[4];
    if ((t & 31) == 0) ws[t >> 5] = ss;
    __syncthreads();
    float scale = 8.0f * rsqrtf(ws[0] + ws[1] + ws[2] + ws[3]);
    for (int f = t; f < NF; f += 128) g_sm[c * NF + f] = semm[c * NF + f] * scale;
}

// ---------------- kernel B: build fused W (tf32-pre-rounded) + bias ----------------
__global__ void k_build(const float* __restrict__ Wcls, const float* __restrict__ bcls,
                        const float* __restrict__ Wsem, const float* __restrict__ bsem,
                        const float* __restrict__ Wbb,  const float* __restrict__ bbb) {
    __shared__ float srow[NF];
    int r = blockIdx.x, t = threadIdx.x;
    if (r == 0) {
        for (int d = t; d < DD; d += 256) g_Wt[d] = to_tf32(Wcls[d]);
        if (t == 0) g_bias[0] = bcls[0];
    } else if (r <= 80) {
        int c = r - 1;
        for (int f = t; f < NF; f += 256) srow[f] = g_sm[c * NF + f];
        __syncthreads();
        float a0 = 0.f, a1 = 0.f, a2 = 0.f, a3 = 0.f;
        for (int f = 0; f < NF; f++) {
            float s = srow[f];
            const float* wp = Wsem + (size_t)f * DD + t;
            a0 += s * wp[0]; a1 += s * wp[256]; a2 += s * wp[512]; a3 += s * wp[768];
        }
        float* wo = g_Wt + (size_t)r * DD + t;
        wo[0] = to_tf32(a0); wo[256] = to_tf32(a1); wo[512] = to_tf32(a2); wo[768] = to_tf32(a3);
        if (t == 0) {
            float b = 0.f;
            for (int f = 0; f < NF; f++) b += srow[f] * bsem[f];
            g_bias[r] = b;
        }
    } else if (r < PCOLS) {
        int i = r - 81;
        for (int d = t; d < DD; d += 256) g_Wt[(size_t)r * DD + d] = to_tf32(Wbb[(size_t)i * DD + d]);
        if (t == 0) g_bias[r] = bbb[i];
    } else {
        for (int d = t; d < DD; d += 256) g_Wt[(size_t)r * DD + d] = 0.f;
        if (t == 0) g_bias[r] = 0.f;
    }
}

// ---------------- main GEMM: raw mma.tf32 + ldmatrix, 256 thr, 3-stage cp.async ----------------
__device__ __forceinline__ void issue_stage(uint32_t sbase, const float* __restrict__ xrow0,
                                            const float* __restrict__ wrow0, int c, int tid) {
    const float* xs = xrow0 + c * BK;
    const float* ws = wrow0 + c * BK;
#pragma unroll
    for (int i = 0; i < 4; i++) {               // A: 128 rows x 8 quads = 1024
        int seg = tid + i * 256;
        int row = seg >> 3, q = seg & 7;
        cpa16(sbase + (uint32_t)(row * 128 + ((q ^ (row & 7)) << 4)),
              xs + (size_t)row * DD + q * 4);
    }
#pragma unroll
    for (int i = 0; i < 3; i++) {               // B: 96 rows x 8 quads = 768
        int seg = tid + i * 256;
        int row = seg >> 3, q = seg & 7;
        cpa16(sbase + (uint32_t)(A_BYTES + row * 128 + ((q ^ (row & 7)) << 4)),
              ws + (size_t)row * DD + q * 4);
    }
    asm volatile("cp.async.commit_group;" ::: "memory");
}

__global__ __launch_bounds__(256, 2) void k_main(const float* __restrict__ x,
                                                 float* __restrict__ out, int N) {
    extern __shared__ char sm[];
    const int tid = threadIdx.x, wid = tid >> 5, lane = tid & 31;
    const int warp_m = wid & 3;        // 4 in M: 32 rows each
    const int warp_n = wid >> 2;       // 2 in N: 48 cols each
    const int nt = blockIdx.x;
    const size_t row0 = (size_t)blockIdx.y * BM;
    const size_t NS = (size_t)N * 81;

    const int col0w = nt * BN + warp_n * 48;
    const int njmax = max(0, min(6, (PCOLS - col0w + 7) >> 3));

    float* sBias = (float*)sm;
    for (int i = tid; i < BN; i += 256) sBias[i] = g_bias[nt * BN + i];

    uint32_t st_u32[NSTAGE];
#pragma unroll
    for (int s = 0; s < NSTAGE; s++) st_u32[s] = smem_u32(sm + 2048 + s * STAGE_SZ);

    const float* xrow0 = x + row0 * DD;
    const float* wrow0 = g_Wt + (size_t)nt * BN * DD;

    int rA[2], rB[3];
    const int qbA = (lane >> 4) & 1;
    const int qbB = (lane >> 3) & 1;
#pragma unroll
    for (int mi = 0; mi < 2; mi++)
        rA[mi] = warp_m * 32 + mi * 16 + ((lane >> 3) & 1) * 8 + (lane & 7);
#pragma unroll
    for (int gj = 0; gj < 3; gj++)
        rB[gj] = warp_n * 48 + gj * 16 + ((lane >> 4) & 1) * 8 + (lane & 7);

    float acc[2][6][4];
#pragma unroll
    for (int mi = 0; mi < 2; mi++)
#pragma unroll
        for (int nj = 0; nj < 6; nj++)
#pragma unroll
            for (int e = 0; e < 4; e++) acc[mi][nj][e] = 0.f;

    issue_stage(st_u32[0], xrow0, wrow0, 0, tid);
    issue_stage(st_u32[1], xrow0, wrow0, 1, tid);

    for (int c = 0; c < NCHUNK; c++) {
        int s = c % NSTAGE;
        if (c == NCHUNK - 1) asm volatile("cp.async.wait_group 0;" ::: "memory");
        else                 asm volatile("cp.async.wait_group 1;" ::: "memory");
        __syncthreads();
        if (c + 2 < NCHUNK)
            issue_stage(st_u32[(c + 2) % NSTAGE], xrow0, wrow0, c + 2, tid);

        if (njmax > 0) {
            const uint32_t Ab = st_u32[s];
            const uint32_t Bb = st_u32[s] + A_BYTES;
#pragma unroll
            for (int kq2 = 0; kq2 < 4; kq2++) {
                uint32_t a[2][4];
#pragma unroll
                for (int mi = 0; mi < 2; mi++) {
                    int r = rA[mi];
                    ldsm4(a[mi], Ab + (uint32_t)(r * 128 + (((2 * kq2 + qbA) ^ (r & 7)) << 4)));
                }
                // NOTE: no cvt on A — mma.tf32 HW reads the tf32 bit-field (RZ truncation).
                uint32_t b[3][4];
#pragma unroll
                for (int gj = 0; gj < 3; gj++) {
                    if (gj * 2 < njmax) {
                        int r = rB[gj];
                        ldsm4(b[gj], Bb + (uint32_t)(r * 128 + (((2 * kq2 + qbB) ^ (r & 7)) << 4)));
                    }
                }
#pragma unroll
                for (int mi = 0; mi < 2; mi++)
#pragma unroll
                    for (int nj = 0; nj < 6; nj++)
                        if (nj < njmax)
                            mma8(acc[mi][nj], a[mi], b[nj >> 1][(nj & 1) * 2], b[nj >> 1][(nj & 1) * 2 + 1]);
            }
        }
    }
    __syncthreads();

    // ---- epilogue: frags -> smem -> biased scatter ----
    float* sC = (float*)(sm + 2048);
    const int tr = lane >> 2, tc2 = (lane & 3) * 2;
#pragma unroll
    for (int mi = 0; mi < 2; mi++)
#pragma unroll
        for (int nj = 0; nj < 6; nj++)
            if (nj < njmax) {
                int r = warp_m * 32 + mi * 16 + tr;
                int cc = warp_n * 48 + nj * 8 + tc2;
                *(float2*)&sC[r * LDC + cc]       = make_float2(acc[mi][nj][0], acc[mi][nj][1]);
                *(float2*)&sC[(r + 8) * LDC + cc] = make_float2(acc[mi][nj][2], acc[mi][nj][3]);
            }
    __syncthreads();

    float* outb = out + NS;
    const int jbase = nt * BN;
    const int ncols = min(BN, PCOLS - jbase);
    for (int e = tid; e < BM * ncols; e += 256) {
        int row = e / ncols, n = e % ncols;
        int j = jbase + n;
        float v = sC[row * LDC + n] + sBias[n];
        size_t gr = row0 + row;
        if (j < 81) out[gr * 81 + j] = v;
        else        outb[gr * 324 + (j - 81)] = v;
    }
}

// ---------------- launch ----------------
extern "C" void kernel_launch(void* const* d_in, const int* in_sizes, int n_in,
                              void* d_out, int out_size) {
    const float* x    = (const float*)d_in[0];
    const float* Wcls = (const float*)d_in[1];
    const float* bcls = (const float*)d_in[2];
    const float* Wsem = (const float*)d_in[3];
    const float* bsem = (const float*)d_in[4];
    const float* Wbb  = (const float*)d_in[5];
    const float* bbb  = (const float*)d_in[6];
    const float* semm = (const float*)d_in[7];
    float* out = (float*)d_out;
    int N = in_sizes[0] / DD;

    cudaFuncSetAttribute(k_main, cudaFuncAttributeMaxDynamicSharedMemorySize, SMEM_DYN);

    k_norm<<<80, 128>>>(semm);
    k_build<<<PPAD, 256>>>(Wcls, bcls, Wsem, bsem, Wbb, bbb);
    dim3 grid(NT, N / BM);
    k_main<<<grid, 256, SMEM_DYN>>>(x, out, N);
}